// round 14
// baseline (speedup 1.0000x reference)
#include <cuda_runtime.h>
#include <cstdint>

#define T_LEN  4096
#define NTH    256
#define PER    16                 // steps per thread; one block per sequence
#define PITCH  257                // smem row pitch for output staging (257 % 32 == 1)

#define DTF    (1.0f / 200.0f)
#define DT2H   (DTF * DTF * 0.5f)
#define STEPDT ((float)PER * DTF)

// scan element: unit quaternion q, v, p.
struct QC { float qw,qx,qy,qz, vx,vy,vz, px,py,pz; };

__device__ __forceinline__ void set_identity(QC& C) {
    C.qw=1.f; C.qx=0.f; C.qy=0.f; C.qz=0.f;
    C.vx=C.vy=C.vz=0.f; C.px=C.py=C.pz=0.f;
}

__device__ __forceinline__ void rot_q(float qw,float qx,float qy,float qz,
                                      float x,float y,float z,
                                      float& rx,float& ry,float& rz) {
    float tx = 2.0f*(qy*z - qz*y);
    float ty = 2.0f*(qz*x - qx*z);
    float tz = 2.0f*(qx*y - qy*x);
    rx = x + qw*tx + (qy*tz - qz*ty);
    ry = y + qw*ty + (qz*tx - qx*tz);
    rz = z + qw*tz + (qx*ty - qy*tx);
}

// C = L compose C (L earlier); span_r = time span covered by C
__device__ __forceinline__ void compose_left(QC& C, const QC& L, float span_r) {
    float qw = L.qw*C.qw - L.qx*C.qx - L.qy*C.qy - L.qz*C.qz;
    float qx = L.qw*C.qx + L.qx*C.qw + L.qy*C.qz - L.qz*C.qy;
    float qy = L.qw*C.qy - L.qx*C.qz + L.qy*C.qw + L.qz*C.qx;
    float qz = L.qw*C.qz + L.qx*C.qy - L.qy*C.qx + L.qz*C.qw;
    float rvx,rvy,rvz; rot_q(L.qw,L.qx,L.qy,L.qz, C.vx,C.vy,C.vz, rvx,rvy,rvz);
    float rpx,rpy,rpz; rot_q(L.qw,L.qx,L.qy,L.qz, C.px,C.py,C.pz, rpx,rpy,rpz);
    C.qw=qw; C.qx=qx; C.qy=qy; C.qz=qz;
    C.vx = L.vx + rvx;  C.vy = L.vy + rvy;  C.vz = L.vz + rvz;
    C.px = L.px + L.vx*span_r + rpx;
    C.py = L.py + L.vy*span_r + rpy;
    C.pz = L.pz + L.vz*span_r + rpz;
}

__device__ __forceinline__ void step_q(QC& C, float wx,float wy,float wz,
                                       float ax,float ay,float az) {
    float n2 = fmaf(wx,wx, fmaf(wy,wy, wz*wz));
    float h2 = n2 * (0.25f * DTF * DTF);
    float dqw = 1.0f - h2*(0.5f - h2*(1.0f/24.0f));
    float s   = (0.5f*DTF) * (1.0f - h2*(1.0f/6.0f - h2*(1.0f/120.0f)));
    float dqx = wx*s, dqy = wy*s, dqz = wz*s;

    float qw = C.qw*dqw - C.qx*dqx - C.qy*dqy - C.qz*dqz;
    float qx = C.qw*dqx + C.qx*dqw + C.qy*dqz - C.qz*dqy;
    float qy = C.qw*dqy - C.qx*dqz + C.qy*dqw + C.qz*dqx;
    float qz = C.qw*dqz + C.qx*dqy - C.qy*dqx + C.qz*dqw;
    C.qw=qw; C.qx=qx; C.qy=qy; C.qz=qz;

    float Rax,Ray,Raz; rot_q(qw,qx,qy,qz, ax,ay,az, Rax,Ray,Raz);

    C.vx += Rax*DTF; C.vy += Ray*DTF; C.vz += Raz*DTF;
    C.px += C.vx*DTF + Rax*DT2H;
    C.py += C.vy*DTF + Ray*DT2H;
    C.pz += C.vz*DTF + Raz*DT2H;
}

__device__ __forceinline__ QC shup(const QC& c, int d) {
    QC r;
    r.qw=__shfl_up_sync(0xffffffffu,c.qw,d);
    r.qx=__shfl_up_sync(0xffffffffu,c.qx,d);
    r.qy=__shfl_up_sync(0xffffffffu,c.qy,d);
    r.qz=__shfl_up_sync(0xffffffffu,c.qz,d);
    r.vx=__shfl_up_sync(0xffffffffu,c.vx,d);
    r.vy=__shfl_up_sync(0xffffffffu,c.vy,d);
    r.vz=__shfl_up_sync(0xffffffffu,c.vz,d);
    r.px=__shfl_up_sync(0xffffffffu,c.px,d);
    r.py=__shfl_up_sync(0xffffffffu,c.py,d);
    r.pz=__shfl_up_sync(0xffffffffu,c.pz,d);
    return r;
}

__device__ __forceinline__ void store_qc(float* m, const QC& C) {
    m[0]=C.qw; m[1]=C.qx; m[2]=C.qy; m[3]=C.qz;
    m[4]=C.vx; m[5]=C.vy; m[6]=C.vz;
    m[7]=C.px; m[8]=C.py; m[9]=C.pz;
}
__device__ __forceinline__ void load_qc(const float* m, QC& C) {
    C.qw=m[0]; C.qx=m[1]; C.qy=m[2]; C.qz=m[3];
    C.vx=m[4]; C.vy=m[5]; C.vz=m[6];
    C.px=m[7]; C.py=m[8]; C.pz=m[9];
}

__global__ void __launch_bounds__(NTH, 4)
preint_kernel(const float* __restrict__ in, float* __restrict__ out) {
    __shared__ float s_buf[32 * PITCH];   // output staging (2 steps x 16ch x 256 owners)
    __shared__ float s_w[8 * 11];         // warp aggregates / prefixes

    const int tid  = threadIdx.x;
    const int lane = tid & 31;
    const int wid  = tid >> 5;
    const int b    = blockIdx.x;          // one block per sequence

    // 24 float4 per thread: chain A = ip[0..11] (steps 0-7), chain B = ip[12..23] (steps 8-15)
    const float4* ip = (const float4*)in
        + (size_t)b * (T_LEN * 6 / 4) + (size_t)tid * (PER * 6 / 4);

    // ---------------- Phase 1: two interleaved 8-step chains (ILP x2), then merge ----------
    QC C, C2;
    set_identity(C);
    set_identity(C2);
#pragma unroll
    for (int j = 0; j < 4; j++) {
        float4 a0 = __ldg(ip + 3*j + 0);
        float4 b0 = __ldg(ip + 12 + 3*j + 0);
        float4 a1 = __ldg(ip + 3*j + 1);
        float4 b1 = __ldg(ip + 12 + 3*j + 1);
        float4 a2 = __ldg(ip + 3*j + 2);
        float4 b2 = __ldg(ip + 12 + 3*j + 2);
        step_q(C,  a0.x, a0.y, a0.z, a0.w, a1.x, a1.y);
        step_q(C2, b0.x, b0.y, b0.z, b0.w, b1.x, b1.y);
        step_q(C,  a1.z, a1.w, a2.x, a2.y, a2.z, a2.w);
        step_q(C2, b1.z, b1.w, b2.x, b2.y, b2.z, b2.w);
    }
    // merge: A (earlier) o B (later); B spans 8 steps
    compose_left(C2, C, 8.0f * DTF);
    C = C2;

    // ---------------- Intra-warp inclusive scan (shuffles) ----------------
#pragma unroll
    for (int dd = 1; dd < 32; dd <<= 1) {
        QC L = shup(C, dd);
        if (lane >= dd) compose_left(C, L, (float)dd * STEPDT);
    }
    if (lane == 31) store_qc(s_w + wid * 11, C);
    __syncthreads();

    // ---------------- Inter-warp scan of 8 aggregates (warp 0) ----------------
    if (wid == 0) {
        QC A;
        if (lane < 8) load_qc(s_w + lane * 11, A);
        else          set_identity(A);
#pragma unroll
        for (int dd = 1; dd < 8; dd <<= 1) {
            QC L = shup(A, dd);
            if (lane >= dd && lane < 8) compose_left(A, L, (float)(dd * 32) * STEPDT);
        }
        if (lane < 8) store_qc(s_w + lane * 11, A);
    }
    __syncthreads();

    // ---------------- Per-thread exclusive prefix ----------------
    {
        QC E = shup(C, 1);
        if (lane == 0) set_identity(E);
        QC W;
        if (wid == 0) set_identity(W);
        else          load_qc(s_w + (wid - 1) * 11, W);
        compose_left(E, W, (float)(lane * PER) * DTF);
        C = E;
    }

    // ---------------- Phase 2: replay (input re-read, L2-hot), coalesced output ------------
    float4* out4 = (float4*)out + (size_t)b * (T_LEN * 4);

#pragma unroll
    for (int g = 0; g < 8; g++) {
        float4 a0 = __ldg(ip + 3*g + 0);
        float4 a1 = __ldg(ip + 3*g + 1);
        float4 a2 = __ldg(ip + 3*g + 2);
        float wxs[2] = {a0.x, a1.z};
        float wys[2] = {a0.y, a1.w};
        float wzs[2] = {a0.z, a2.x};
        float axs[2] = {a0.w, a2.y};
        float ays[2] = {a1.x, a2.z};
        float azs[2] = {a1.y, a2.w};

#pragma unroll
        for (int k = 0; k < 2; k++) {
            step_q(C, wxs[k], wys[k], wzs[k], axs[k], ays[k], azs[k]);

            // output quaternion = carry, renormalized, sign-fixed (qw >= 0)
            float n  = fmaf(C.qw,C.qw, fmaf(C.qx,C.qx, fmaf(C.qy,C.qy, C.qz*C.qz)));
            float rn = rsqrtf(n);
            rn = (C.qw < 0.0f) ? -rn : rn;
            float qw = C.qw*rn, qx = C.qx*rn, qy = C.qy*rn, qz = C.qz*rn;

            float* dst = s_buf + (k * 16) * PITCH + tid;
            dst[0*PITCH]  = wxs[k]; dst[1*PITCH]  = wys[k]; dst[2*PITCH]  = wzs[k];
            dst[3*PITCH]  = axs[k]; dst[4*PITCH]  = ays[k]; dst[5*PITCH]  = azs[k];
            dst[6*PITCH]  = C.px;   dst[7*PITCH]  = C.py;   dst[8*PITCH]  = C.pz;
            dst[9*PITCH]  = qw;     dst[10*PITCH] = qx;     dst[11*PITCH] = qy;
            dst[12*PITCH] = qz;
            dst[13*PITCH] = C.vx;   dst[14*PITCH] = C.vy;   dst[15*PITCH] = C.vz;
        }
        __syncthreads();

        // coalesced flush: 2 steps x 256 owners = 2048 float4, 8 per thread
#pragma unroll
        for (int r = 0; r < 8; r++) {
            int f  = tid + NTH * r;
            int o  = f >> 3;
            int mq = f & 7;
            const float* s = s_buf + (mq * 4) * PITCH + o;
            float4 v = make_float4(s[0*PITCH], s[1*PITCH], s[2*PITCH], s[3*PITCH]);
            out4[(size_t)o * (PER * 4) + g * 8 + mq] = v;
        }
        __syncthreads();
    }
}

extern "C" void kernel_launch(void* const* d_in, const int* in_sizes, int n_in,
                              void* d_out, int out_size) {
    const float* in = (const float*)d_in[0];
    float* out = (float*)d_out;
    int Bn = in_sizes[0] / (T_LEN * 6);   // 512 for the reference shapes
    preint_kernel<<<Bn, NTH>>>(in, out);
}